// round 11
// baseline (speedup 1.0000x reference)
#include <cuda_runtime.h>
#include <cuda_bf16.h>

// BaseSpanProposer: analytic span compaction.
// viable[b,s,l] = (s + l) < len_b. nonzero order = ascending flattened index,
// computable in closed form via per-batch prefix sums. Padding rows -> flat 0.
//
// R2: unit-id stores transposed to block-cooperative contiguous float4 writes.
// R3: fused kernel, per-block warp-shfl prefix scan, compile-time S/L.
// R4: 4 rows/thread so all nine scalar arrays store as STG.128; quad mapping.
// R9: drop the ext-table kernel (its launch cost > savings); clamp+I2F inlined
//     back into the chunk loop — lands in idle issue slots (issue was 37%).

#define TPB 256
#define RPT 4
#define ROWS_PER_BLOCK (TPB * RPT)

// Specialized path constants (B=128, S=512, L=20)
#define SP_B 128
#define SP_S 512
#define SP_L 20

// ---------------- specialized fused kernel ----------------
__global__ void __launch_bounds__(TPB)
span_main_kernel(const int* __restrict__ seqs,
                 const int* __restrict__ lens,
                 const float* __restrict__ pw,
                 float* __restrict__ out,
                 int N) {
    const int B = SP_B, S = SP_S, L = SP_L;

    __shared__ int sp[TPB + 1];
    __shared__ int sl[TPB];
    __shared__ int wsum[TPB / 32];
    __shared__ int wmax[TPB / 32];
    __shared__ int rBS[ROWS_PER_BLOCK];   // per-row packed (b<<16)|s

    const int tid = threadIdx.x;
    const int lane = tid & 31;
    const int warp = tid >> 5;

    // ---- per-block redundant prefix scan over per-batch viable counts ----
    int len = 0, cnt = 0;
    if (tid < B) {
        len = lens[tid];
        cnt = (len >= L) ? (len - L + 1) * L + (L * (L - 1)) / 2
                         : (len * (len + 1)) / 2;
    }
    int scn = cnt;
    #pragma unroll
    for (int o = 1; o < 32; o <<= 1) {
        int v = __shfl_up_sync(0xffffffffu, scn, o);
        if (lane >= o) scn += v;
    }
    int lmax = len;
    #pragma unroll
    for (int o = 16; o > 0; o >>= 1)
        lmax = max(lmax, __shfl_xor_sync(0xffffffffu, lmax, o));
    if (lane == 31) wsum[warp] = scn;
    if (lane == 0)  wmax[warp] = lmax;
    __syncthreads();
    int off = 0;
    #pragma unroll
    for (int k = 0; k < TPB / 32; k++) if (k < warp) off += wsum[k];
    if (tid < B) { sp[tid + 1] = scn + off; sl[tid] = len; }
    if (tid == 0) sp[0] = 0;
    int maxlen = 0;
    #pragma unroll
    for (int k = 0; k < TPB / 32; k++) maxlen = max(maxlen, wmax[k]);
    __syncthreads();

    const int total = sp[B];
    const int maxpos = maxlen - 1;
    const size_t Nz = (size_t)N;
    const int base_row = blockIdx.x * ROWS_PER_BLOCK;
    const int i0 = base_row + tid * RPT;

    int rb[RPT], rs[RPT], rl[RPT];

    if (i0 < N) {
        // ---- map first row of quad ----
        int b = 0, s = 0, l = 0, lb = 0, c = 1;
        if (i0 < total) {
            int lo = 0, hi = B - 1;
            while (lo < hi) {
                int mid = (lo + hi + 1) >> 1;
                if (sp[mid] <= i0) lo = mid; else hi = mid - 1;
            }
            b = lo;
            int j = i0 - sp[b];
            lb = sl[b];
            int full = lb - L + 1;
            if (full > 0 && j < full * L) {
                s = (unsigned)j / (unsigned)L;
                l = j - s * L;
            } else {
                int s0 = full > 0 ? full : 0;
                int jp = j - (full > 0 ? full * L : 0);
                int ss = s0, acc = 0;
                while (true) {
                    int m = lb - ss; if (m > L) m = L;
                    if (jp < acc + m) { l = jp - acc; break; }
                    acc += m; ss++;
                }
                s = ss;
            }
            c = lb - s; if (c > L) c = L;
        }

        if (i0 + RPT - 1 < total && l + RPT - 1 < c) {
            // fast path: whole quad in one (b,s) run
            #pragma unroll
            for (int k = 0; k < RPT; k++) { rb[k] = b; rs[k] = s; rl[k] = l + k; }
        } else {
            #pragma unroll
            for (int k = 0; k < RPT; k++) {
                int i = i0 + k;
                if (i >= total) { rb[k] = 0; rs[k] = 0; rl[k] = 0; continue; }
                if (k > 0) {
                    l++;
                    if (l >= c) {
                        l = 0; s++;
                        while (s >= lb) { b++; lb = sl[b]; s = 0; }
                        c = lb - s; if (c > L) c = L;
                    }
                }
                rb[k] = b; rs[k] = s; rl[k] = l;
            }
        }

        // ---- candidate arrays (quad-aligned: lc in {0,4,8,12,16}) ----
        unsigned u = (unsigned)i0;
        int bc = u / (unsigned)(S * L);
        int rm = i0 - bc * (S * L);
        int sc = (unsigned)rm / (unsigned)L;
        int lc = rm - sc * L;
        int d = sl[bc] - sc - lc;         // viable_k = (k < d)

        float4 vv;
        vv.x = (d > 0) ? 1.0f : 0.0f;
        vv.y = (d > 1) ? 1.0f : 0.0f;
        vv.z = (d > 2) ? 1.0f : 0.0f;
        vv.w = (d > 3) ? 1.0f : 0.0f;
        float eb = (float)(sc + lc);
        float lnb = (float)(lc + 1);
        float fsc = (float)sc;
        float4 scv = make_float4(fsc, fsc, fsc, fsc);
        float4 ecv = make_float4(eb, eb + 1.f, eb + 2.f, eb + 3.f);
        float4 lnv = make_float4(lnb, lnb + 1.f, lnb + 2.f, lnb + 3.f);

        // ---- mapped arrays ----
        float4 fb, fs, fe, fl, pwv;
        fb.x = (float)rb[0]; fb.y = (float)rb[1]; fb.z = (float)rb[2]; fb.w = (float)rb[3];
        fs.x = (float)rs[0]; fs.y = (float)rs[1]; fs.z = (float)rs[2]; fs.w = (float)rs[3];
        fe.x = (float)(rs[0] + rl[0]); fe.y = (float)(rs[1] + rl[1]);
        fe.z = (float)(rs[2] + rl[2]); fe.w = (float)(rs[3] + rl[3]);
        fl.x = (float)(rl[0] + 1); fl.y = (float)(rl[1] + 1);
        fl.z = (float)(rl[2] + 1); fl.w = (float)(rl[3] + 1);
        pwv.x = pw[(rb[0] * S + rs[0]) * L + rl[0]];
        pwv.y = pw[(rb[1] * S + rs[1]) * L + rl[1]];
        pwv.z = pw[(rb[2] * S + rs[2]) * L + rl[2]];
        pwv.w = pw[(rb[3] * S + rs[3]) * L + rl[3]];

        size_t off6 = 5 * Nz + Nz * (size_t)L;
        __stcs((float4*)(out + i0),              vv);
        __stcs((float4*)(out + Nz + i0),         fb);
        __stcs((float4*)(out + 2 * Nz + i0),     fs);
        __stcs((float4*)(out + 3 * Nz + i0),     fe);
        __stcs((float4*)(out + 4 * Nz + i0),     fl);
        __stcs((float4*)(out + off6 + i0),       pwv);
        __stcs((float4*)(out + off6 + Nz + i0),  scv);
        __stcs((float4*)(out + off6 + 2 * Nz + i0), ecv);
        __stcs((float4*)(out + off6 + 3 * Nz + i0), lnv);

        #pragma unroll
        for (int k = 0; k < RPT; k++)
            rBS[tid * RPT + k] = (rb[k] << 16) | rs[k];
    } else {
        #pragma unroll
        for (int k = 0; k < RPT; k++) rBS[tid * RPT + k] = 0;
    }
    __syncthreads();

    // ---- unit-id matrix: block-cooperative contiguous float4 stores ----
    int nrows = N - base_row; if (nrows > ROWS_PER_BLOCK) nrows = ROWS_PER_BLOCK;
    const int nchunks = nrows * 5;
    float* ubase = out + 5 * Nz + (size_t)base_row * L;

    #pragma unroll
    for (int pass = 0; pass < RPT * 5; pass++) {
        int e = pass * TPB + tid;
        if (e < nchunks) {
            int r = (unsigned)e / 5u;
            int j = (e - r * 5) << 2;
            int bs = rBS[r];
            int s_r = bs & 0xffff;
            const int* row = seqs + (size_t)(bs >> 16) * S;
            int p0 = s_r + j;     if (p0 > maxpos) p0 = maxpos;
            int p1 = s_r + j + 1; if (p1 > maxpos) p1 = maxpos;
            int p2 = s_r + j + 2; if (p2 > maxpos) p2 = maxpos;
            int p3 = s_r + j + 3; if (p3 > maxpos) p3 = maxpos;
            float4 v;
            v.x = (float)__ldg(row + p0);
            v.y = (float)__ldg(row + p1);
            v.z = (float)__ldg(row + p2);
            v.w = (float)__ldg(row + p3);
            __stcs((float4*)(ubase + (size_t)r * L + j), v);
        }
    }
}

// ---------------- generic fallback ----------------
__global__ void __launch_bounds__(TPB)
span_generic_kernel(const int* __restrict__ seqs,
                    const int* __restrict__ lens,
                    const float* __restrict__ pw,
                    float* __restrict__ out,
                    int B, int S, int L, int N) {
    __shared__ int sp[TPB + 1];
    __shared__ int sl[TPB];
    __shared__ int wsum[8];
    __shared__ int wmax[8];
    __shared__ int rBS[TPB];

    const int tid = threadIdx.x;
    const int lane = tid & 31;
    const int warp = tid >> 5;

    int len = 0, cnt = 0;
    if (tid < B) {
        len = lens[tid];
        cnt = (len >= L) ? (len - L + 1) * L + (L * (L - 1)) / 2
                         : (len * (len + 1)) / 2;
    }
    int scn = cnt;
    #pragma unroll
    for (int o = 1; o < 32; o <<= 1) {
        int v = __shfl_up_sync(0xffffffffu, scn, o);
        if (lane >= o) scn += v;
    }
    int lmax = len;
    #pragma unroll
    for (int o = 16; o > 0; o >>= 1)
        lmax = max(lmax, __shfl_xor_sync(0xffffffffu, lmax, o));
    if (lane == 31) wsum[warp] = scn;
    if (lane == 0)  wmax[warp] = lmax;
    __syncthreads();
    int off = 0;
    #pragma unroll
    for (int k = 0; k < 8; k++) if (k < warp) off += wsum[k];
    if (tid < B) { sp[tid + 1] = scn + off; sl[tid] = len; }
    if (tid == 0) sp[0] = 0;
    int maxlen = 0;
    #pragma unroll
    for (int k = 0; k < 8; k++) maxlen = max(maxlen, wmax[k]);
    __syncthreads();

    const int i = blockIdx.x * TPB + tid;
    const int total = sp[B];
    const int maxpos = maxlen - 1;
    const size_t Nz = (size_t)N;

    int b = 0, s = 0, l = 0;
    if (i < N) {
        if (i < total) {
            int lo = 0, hi = B - 1;
            while (lo < hi) {
                int mid = (lo + hi + 1) >> 1;
                if (sp[mid] <= i) lo = mid; else hi = mid - 1;
            }
            b = lo;
            int j = i - sp[b];
            int lb = sl[b];
            int full = lb - L + 1;
            if (full > 0 && j < full * L) {
                s = j / L;
                l = j - s * L;
            } else {
                int s0 = full > 0 ? full : 0;
                int jp = j - (full > 0 ? full * L : 0);
                int ss = s0, c = 0;
                while (true) {
                    int m = lb - ss; if (m > L) m = L;
                    if (jp < c + m) { l = jp - c; break; }
                    c += m; ss++;
                }
                s = ss;
            }
        }

        int SL = S * L;
        int bc = i / SL;
        int rem = i - bc * SL;
        int sc = rem / L;
        int lc = rem - sc * L;
        float viable_f = ((sc + lc) < sl[bc]) ? 1.0f : 0.0f;

        out[i]          = viable_f;
        out[Nz + i]     = (float)b;
        out[2 * Nz + i] = (float)s;
        out[3 * Nz + i] = (float)(s + l);
        out[4 * Nz + i] = (float)(l + 1);

        size_t off6 = 5 * Nz + Nz * (size_t)L;
        out[off6 + i]          = pw[((size_t)b * S + s) * L + l];
        out[off6 + Nz + i]     = (float)sc;
        out[off6 + 2 * Nz + i] = (float)(sc + lc);
        out[off6 + 3 * Nz + i] = (float)(lc + 1);
    }

    rBS[tid] = (b << 16) | s;
    __syncthreads();

    const int base_row = blockIdx.x * TPB;
    int nrows = N - base_row; if (nrows > TPB) nrows = TPB;

    for (int e = tid; e < nrows * L; e += TPB) {
        int r = e / L;
        int j = e - r * L;
        int bs = rBS[r];
        int p = (bs & 0xffff) + j; if (p > maxpos) p = maxpos;
        out[5 * Nz + (size_t)(base_row + r) * L + j] =
            (float)seqs[(size_t)(bs >> 16) * S + p];
    }
}

extern "C" void kernel_launch(void* const* d_in, const int* in_sizes, int n_in,
                              void* d_out, int out_size) {
    const int* seqs = (const int*)d_in[0];   // (B, S) int32
    const int* lens = (const int*)d_in[1];   // (B,)   int32
    const float* pw = (const float*)d_in[2]; // (B, S, L) float32

    int B = in_sizes[1];
    int S = in_sizes[0] / B;
    int N = in_sizes[2];          // B*S*L
    int L = N / (B * S);
    float* out = (float*)d_out;

    if (B == SP_B && S == SP_S && L == SP_L) {
        int blocks = (N + ROWS_PER_BLOCK - 1) / ROWS_PER_BLOCK;
        span_main_kernel<<<blocks, TPB>>>(seqs, lens, pw, out, N);
    } else {
        int blocks = (N + TPB - 1) / TPB;
        span_generic_kernel<<<blocks, TPB>>>(seqs, lens, pw, out, B, S, L, N);
    }
}

// round 12
// speedup vs baseline: 1.0034x; 1.0034x over previous
#include <cuda_runtime.h>
#include <cuda_bf16.h>

// BaseSpanProposer: analytic span compaction.
// viable[b,s,l] = (s + l) < len_b. nonzero order = ascending flattened index,
// computable in closed form via per-batch prefix sums. Padding rows -> flat 0.
//
// R2: unit-id stores transposed to block-cooperative contiguous float4 writes.
// R3: fused kernel, per-block warp-shfl prefix scan, compile-time S/L.
// R4: 4 rows/thread so all nine scalar arrays store as STG.128; quad mapping.
// R9: drop the ext-table kernel (its launch cost > savings); clamp+I2F inlined
//     back into the chunk loop — lands in idle issue slots (issue was 37%).

#define TPB 256
#define RPT 4
#define ROWS_PER_BLOCK (TPB * RPT)

// Specialized path constants (B=128, S=512, L=20)
#define SP_B 128
#define SP_S 512
#define SP_L 20

// ---------------- specialized fused kernel ----------------
__global__ void __launch_bounds__(TPB)
span_main_kernel(const int* __restrict__ seqs,
                 const int* __restrict__ lens,
                 const float* __restrict__ pw,
                 float* __restrict__ out,
                 int N) {
    const int B = SP_B, S = SP_S, L = SP_L;

    __shared__ int sp[TPB + 1];
    __shared__ int sl[TPB];
    __shared__ int wsum[TPB / 32];
    __shared__ int wmax[TPB / 32];
    __shared__ int rBS[ROWS_PER_BLOCK];   // per-row packed (b<<16)|s

    const int tid = threadIdx.x;
    const int lane = tid & 31;
    const int warp = tid >> 5;

    // ---- per-block redundant prefix scan over per-batch viable counts ----
    int len = 0, cnt = 0;
    if (tid < B) {
        len = lens[tid];
        cnt = (len >= L) ? (len - L + 1) * L + (L * (L - 1)) / 2
                         : (len * (len + 1)) / 2;
    }
    int scn = cnt;
    #pragma unroll
    for (int o = 1; o < 32; o <<= 1) {
        int v = __shfl_up_sync(0xffffffffu, scn, o);
        if (lane >= o) scn += v;
    }
    int lmax = len;
    #pragma unroll
    for (int o = 16; o > 0; o >>= 1)
        lmax = max(lmax, __shfl_xor_sync(0xffffffffu, lmax, o));
    if (lane == 31) wsum[warp] = scn;
    if (lane == 0)  wmax[warp] = lmax;
    __syncthreads();
    int off = 0;
    #pragma unroll
    for (int k = 0; k < TPB / 32; k++) if (k < warp) off += wsum[k];
    if (tid < B) { sp[tid + 1] = scn + off; sl[tid] = len; }
    if (tid == 0) sp[0] = 0;
    int maxlen = 0;
    #pragma unroll
    for (int k = 0; k < TPB / 32; k++) maxlen = max(maxlen, wmax[k]);
    __syncthreads();

    const int total = sp[B];
    const int maxpos = maxlen - 1;
    const size_t Nz = (size_t)N;
    const int base_row = blockIdx.x * ROWS_PER_BLOCK;
    const int i0 = base_row + tid * RPT;

    int rb[RPT], rs[RPT], rl[RPT];

    if (i0 < N) {
        // ---- map first row of quad ----
        int b = 0, s = 0, l = 0, lb = 0, c = 1;
        if (i0 < total) {
            int lo = 0, hi = B - 1;
            while (lo < hi) {
                int mid = (lo + hi + 1) >> 1;
                if (sp[mid] <= i0) lo = mid; else hi = mid - 1;
            }
            b = lo;
            int j = i0 - sp[b];
            lb = sl[b];
            int full = lb - L + 1;
            if (full > 0 && j < full * L) {
                s = (unsigned)j / (unsigned)L;
                l = j - s * L;
            } else {
                int s0 = full > 0 ? full : 0;
                int jp = j - (full > 0 ? full * L : 0);
                int ss = s0, acc = 0;
                while (true) {
                    int m = lb - ss; if (m > L) m = L;
                    if (jp < acc + m) { l = jp - acc; break; }
                    acc += m; ss++;
                }
                s = ss;
            }
            c = lb - s; if (c > L) c = L;
        }

        if (i0 + RPT - 1 < total && l + RPT - 1 < c) {
            // fast path: whole quad in one (b,s) run
            #pragma unroll
            for (int k = 0; k < RPT; k++) { rb[k] = b; rs[k] = s; rl[k] = l + k; }
        } else {
            #pragma unroll
            for (int k = 0; k < RPT; k++) {
                int i = i0 + k;
                if (i >= total) { rb[k] = 0; rs[k] = 0; rl[k] = 0; continue; }
                if (k > 0) {
                    l++;
                    if (l >= c) {
                        l = 0; s++;
                        while (s >= lb) { b++; lb = sl[b]; s = 0; }
                        c = lb - s; if (c > L) c = L;
                    }
                }
                rb[k] = b; rs[k] = s; rl[k] = l;
            }
        }

        // ---- candidate arrays (quad-aligned: lc in {0,4,8,12,16}) ----
        unsigned u = (unsigned)i0;
        int bc = u / (unsigned)(S * L);
        int rm = i0 - bc * (S * L);
        int sc = (unsigned)rm / (unsigned)L;
        int lc = rm - sc * L;
        int d = sl[bc] - sc - lc;         // viable_k = (k < d)

        float4 vv;
        vv.x = (d > 0) ? 1.0f : 0.0f;
        vv.y = (d > 1) ? 1.0f : 0.0f;
        vv.z = (d > 2) ? 1.0f : 0.0f;
        vv.w = (d > 3) ? 1.0f : 0.0f;
        float eb = (float)(sc + lc);
        float lnb = (float)(lc + 1);
        float fsc = (float)sc;
        float4 scv = make_float4(fsc, fsc, fsc, fsc);
        float4 ecv = make_float4(eb, eb + 1.f, eb + 2.f, eb + 3.f);
        float4 lnv = make_float4(lnb, lnb + 1.f, lnb + 2.f, lnb + 3.f);

        // ---- mapped arrays ----
        float4 fb, fs, fe, fl, pwv;
        fb.x = (float)rb[0]; fb.y = (float)rb[1]; fb.z = (float)rb[2]; fb.w = (float)rb[3];
        fs.x = (float)rs[0]; fs.y = (float)rs[1]; fs.z = (float)rs[2]; fs.w = (float)rs[3];
        fe.x = (float)(rs[0] + rl[0]); fe.y = (float)(rs[1] + rl[1]);
        fe.z = (float)(rs[2] + rl[2]); fe.w = (float)(rs[3] + rl[3]);
        fl.x = (float)(rl[0] + 1); fl.y = (float)(rl[1] + 1);
        fl.z = (float)(rl[2] + 1); fl.w = (float)(rl[3] + 1);
        pwv.x = pw[(rb[0] * S + rs[0]) * L + rl[0]];
        pwv.y = pw[(rb[1] * S + rs[1]) * L + rl[1]];
        pwv.z = pw[(rb[2] * S + rs[2]) * L + rl[2]];
        pwv.w = pw[(rb[3] * S + rs[3]) * L + rl[3]];

        size_t off6 = 5 * Nz + Nz * (size_t)L;
        __stcs((float4*)(out + i0),              vv);
        __stcs((float4*)(out + Nz + i0),         fb);
        __stcs((float4*)(out + 2 * Nz + i0),     fs);
        __stcs((float4*)(out + 3 * Nz + i0),     fe);
        __stcs((float4*)(out + 4 * Nz + i0),     fl);
        __stcs((float4*)(out + off6 + i0),       pwv);
        __stcs((float4*)(out + off6 + Nz + i0),  scv);
        __stcs((float4*)(out + off6 + 2 * Nz + i0), ecv);
        __stcs((float4*)(out + off6 + 3 * Nz + i0), lnv);

        #pragma unroll
        for (int k = 0; k < RPT; k++)
            rBS[tid * RPT + k] = (rb[k] << 16) | rs[k];
    } else {
        #pragma unroll
        for (int k = 0; k < RPT; k++) rBS[tid * RPT + k] = 0;
    }
    __syncthreads();

    // ---- unit-id matrix: block-cooperative contiguous float4 stores ----
    int nrows = N - base_row; if (nrows > ROWS_PER_BLOCK) nrows = ROWS_PER_BLOCK;
    const int nchunks = nrows * 5;
    float* ubase = out + 5 * Nz + (size_t)base_row * L;

    #pragma unroll
    for (int pass = 0; pass < RPT * 5; pass++) {
        int e = pass * TPB + tid;
        if (e < nchunks) {
            int r = (unsigned)e / 5u;
            int j = (e - r * 5) << 2;
            int bs = rBS[r];
            int s_r = bs & 0xffff;
            const int* row = seqs + (size_t)(bs >> 16) * S;
            int p0 = s_r + j;     if (p0 > maxpos) p0 = maxpos;
            int p1 = s_r + j + 1; if (p1 > maxpos) p1 = maxpos;
            int p2 = s_r + j + 2; if (p2 > maxpos) p2 = maxpos;
            int p3 = s_r + j + 3; if (p3 > maxpos) p3 = maxpos;
            float4 v;
            v.x = (float)__ldg(row + p0);
            v.y = (float)__ldg(row + p1);
            v.z = (float)__ldg(row + p2);
            v.w = (float)__ldg(row + p3);
            __stcs((float4*)(ubase + (size_t)r * L + j), v);
        }
    }
}

// ---------------- generic fallback ----------------
__global__ void __launch_bounds__(TPB)
span_generic_kernel(const int* __restrict__ seqs,
                    const int* __restrict__ lens,
                    const float* __restrict__ pw,
                    float* __restrict__ out,
                    int B, int S, int L, int N) {
    __shared__ int sp[TPB + 1];
    __shared__ int sl[TPB];
    __shared__ int wsum[8];
    __shared__ int wmax[8];
    __shared__ int rBS[TPB];

    const int tid = threadIdx.x;
    const int lane = tid & 31;
    const int warp = tid >> 5;

    int len = 0, cnt = 0;
    if (tid < B) {
        len = lens[tid];
        cnt = (len >= L) ? (len - L + 1) * L + (L * (L - 1)) / 2
                         : (len * (len + 1)) / 2;
    }
    int scn = cnt;
    #pragma unroll
    for (int o = 1; o < 32; o <<= 1) {
        int v = __shfl_up_sync(0xffffffffu, scn, o);
        if (lane >= o) scn += v;
    }
    int lmax = len;
    #pragma unroll
    for (int o = 16; o > 0; o >>= 1)
        lmax = max(lmax, __shfl_xor_sync(0xffffffffu, lmax, o));
    if (lane == 31) wsum[warp] = scn;
    if (lane == 0)  wmax[warp] = lmax;
    __syncthreads();
    int off = 0;
    #pragma unroll
    for (int k = 0; k < 8; k++) if (k < warp) off += wsum[k];
    if (tid < B) { sp[tid + 1] = scn + off; sl[tid] = len; }
    if (tid == 0) sp[0] = 0;
    int maxlen = 0;
    #pragma unroll
    for (int k = 0; k < 8; k++) maxlen = max(maxlen, wmax[k]);
    __syncthreads();

    const int i = blockIdx.x * TPB + tid;
    const int total = sp[B];
    const int maxpos = maxlen - 1;
    const size_t Nz = (size_t)N;

    int b = 0, s = 0, l = 0;
    if (i < N) {
        if (i < total) {
            int lo = 0, hi = B - 1;
            while (lo < hi) {
                int mid = (lo + hi + 1) >> 1;
                if (sp[mid] <= i) lo = mid; else hi = mid - 1;
            }
            b = lo;
            int j = i - sp[b];
            int lb = sl[b];
            int full = lb - L + 1;
            if (full > 0 && j < full * L) {
                s = j / L;
                l = j - s * L;
            } else {
                int s0 = full > 0 ? full : 0;
                int jp = j - (full > 0 ? full * L : 0);
                int ss = s0, c = 0;
                while (true) {
                    int m = lb - ss; if (m > L) m = L;
                    if (jp < c + m) { l = jp - c; break; }
                    c += m; ss++;
                }
                s = ss;
            }
        }

        int SL = S * L;
        int bc = i / SL;
        int rem = i - bc * SL;
        int sc = rem / L;
        int lc = rem - sc * L;
        float viable_f = ((sc + lc) < sl[bc]) ? 1.0f : 0.0f;

        out[i]          = viable_f;
        out[Nz + i]     = (float)b;
        out[2 * Nz + i] = (float)s;
        out[3 * Nz + i] = (float)(s + l);
        out[4 * Nz + i] = (float)(l + 1);

        size_t off6 = 5 * Nz + Nz * (size_t)L;
        out[off6 + i]          = pw[((size_t)b * S + s) * L + l];
        out[off6 + Nz + i]     = (float)sc;
        out[off6 + 2 * Nz + i] = (float)(sc + lc);
        out[off6 + 3 * Nz + i] = (float)(lc + 1);
    }

    rBS[tid] = (b << 16) | s;
    __syncthreads();

    const int base_row = blockIdx.x * TPB;
    int nrows = N - base_row; if (nrows > TPB) nrows = TPB;

    for (int e = tid; e < nrows * L; e += TPB) {
        int r = e / L;
        int j = e - r * L;
        int bs = rBS[r];
        int p = (bs & 0xffff) + j; if (p > maxpos) p = maxpos;
        out[5 * Nz + (size_t)(base_row + r) * L + j] =
            (float)seqs[(size_t)(bs >> 16) * S + p];
    }
}

extern "C" void kernel_launch(void* const* d_in, const int* in_sizes, int n_in,
                              void* d_out, int out_size) {
    const int* seqs = (const int*)d_in[0];   // (B, S) int32
    const int* lens = (const int*)d_in[1];   // (B,)   int32
    const float* pw = (const float*)d_in[2]; // (B, S, L) float32

    int B = in_sizes[1];
    int S = in_sizes[0] / B;
    int N = in_sizes[2];          // B*S*L
    int L = N / (B * S);
    float* out = (float*)d_out;

    if (B == SP_B && S == SP_S && L == SP_L) {
        int blocks = (N + ROWS_PER_BLOCK - 1) / ROWS_PER_BLOCK;
        span_main_kernel<<<blocks, TPB>>>(seqs, lens, pw, out, N);
    } else {
        int blocks = (N + TPB - 1) / TPB;
        span_generic_kernel<<<blocks, TPB>>>(seqs, lens, pw, out, B, S, L, N);
    }
}

// round 13
// speedup vs baseline: 1.0590x; 1.0554x over previous
#include <cuda_runtime.h>
#include <cuda_bf16.h>

// BaseSpanProposer: analytic span compaction.
// viable[b,s,l] = (s + l) < len_b. nonzero order = ascending flattened index,
// computable in closed form via per-batch prefix sums. Padding rows -> flat 0.
//
// R2: unit-id stores transposed to block-cooperative contiguous float4 writes.
// R3: fused kernel, per-block warp-shfl prefix scan, compile-time S/L.
// R4: 4 rows/thread so all nine scalar arrays store as STG.128; quad mapping.
// R9: drop the ext-table kernel (its launch cost > savings); clamp+I2F inlined
//     back into the chunk loop — lands in idle issue slots (issue was 37%).

#define TPB 256
#define RPT 4
#define ROWS_PER_BLOCK (TPB * RPT)

// Specialized path constants (B=128, S=512, L=20)
#define SP_B 128
#define SP_S 512
#define SP_L 20

// ---------------- specialized fused kernel ----------------
__global__ void __launch_bounds__(TPB)
span_main_kernel(const int* __restrict__ seqs,
                 const int* __restrict__ lens,
                 const float* __restrict__ pw,
                 float* __restrict__ out,
                 int N) {
    const int B = SP_B, S = SP_S, L = SP_L;

    __shared__ int sp[TPB + 1];
    __shared__ int sl[TPB];
    __shared__ int wsum[TPB / 32];
    __shared__ int wmax[TPB / 32];
    __shared__ int rBS[ROWS_PER_BLOCK];   // per-row packed (b<<16)|s

    const int tid = threadIdx.x;
    const int lane = tid & 31;
    const int warp = tid >> 5;

    // ---- per-block redundant prefix scan over per-batch viable counts ----
    int len = 0, cnt = 0;
    if (tid < B) {
        len = lens[tid];
        cnt = (len >= L) ? (len - L + 1) * L + (L * (L - 1)) / 2
                         : (len * (len + 1)) / 2;
    }
    int scn = cnt;
    #pragma unroll
    for (int o = 1; o < 32; o <<= 1) {
        int v = __shfl_up_sync(0xffffffffu, scn, o);
        if (lane >= o) scn += v;
    }
    int lmax = len;
    #pragma unroll
    for (int o = 16; o > 0; o >>= 1)
        lmax = max(lmax, __shfl_xor_sync(0xffffffffu, lmax, o));
    if (lane == 31) wsum[warp] = scn;
    if (lane == 0)  wmax[warp] = lmax;
    __syncthreads();
    int off = 0;
    #pragma unroll
    for (int k = 0; k < TPB / 32; k++) if (k < warp) off += wsum[k];
    if (tid < B) { sp[tid + 1] = scn + off; sl[tid] = len; }
    if (tid == 0) sp[0] = 0;
    int maxlen = 0;
    #pragma unroll
    for (int k = 0; k < TPB / 32; k++) maxlen = max(maxlen, wmax[k]);
    __syncthreads();

    const int total = sp[B];
    const int maxpos = maxlen - 1;
    const size_t Nz = (size_t)N;
    const int base_row = blockIdx.x * ROWS_PER_BLOCK;
    const int i0 = base_row + tid * RPT;

    int rb[RPT], rs[RPT], rl[RPT];

    if (i0 < N) {
        // ---- map first row of quad ----
        int b = 0, s = 0, l = 0, lb = 0, c = 1;
        if (i0 < total) {
            int lo = 0, hi = B - 1;
            while (lo < hi) {
                int mid = (lo + hi + 1) >> 1;
                if (sp[mid] <= i0) lo = mid; else hi = mid - 1;
            }
            b = lo;
            int j = i0 - sp[b];
            lb = sl[b];
            int full = lb - L + 1;
            if (full > 0 && j < full * L) {
                s = (unsigned)j / (unsigned)L;
                l = j - s * L;
            } else {
                int s0 = full > 0 ? full : 0;
                int jp = j - (full > 0 ? full * L : 0);
                int ss = s0, acc = 0;
                while (true) {
                    int m = lb - ss; if (m > L) m = L;
                    if (jp < acc + m) { l = jp - acc; break; }
                    acc += m; ss++;
                }
                s = ss;
            }
            c = lb - s; if (c > L) c = L;
        }

        if (i0 + RPT - 1 < total && l + RPT - 1 < c) {
            // fast path: whole quad in one (b,s) run
            #pragma unroll
            for (int k = 0; k < RPT; k++) { rb[k] = b; rs[k] = s; rl[k] = l + k; }
        } else {
            #pragma unroll
            for (int k = 0; k < RPT; k++) {
                int i = i0 + k;
                if (i >= total) { rb[k] = 0; rs[k] = 0; rl[k] = 0; continue; }
                if (k > 0) {
                    l++;
                    if (l >= c) {
                        l = 0; s++;
                        while (s >= lb) { b++; lb = sl[b]; s = 0; }
                        c = lb - s; if (c > L) c = L;
                    }
                }
                rb[k] = b; rs[k] = s; rl[k] = l;
            }
        }

        // ---- candidate arrays (quad-aligned: lc in {0,4,8,12,16}) ----
        unsigned u = (unsigned)i0;
        int bc = u / (unsigned)(S * L);
        int rm = i0 - bc * (S * L);
        int sc = (unsigned)rm / (unsigned)L;
        int lc = rm - sc * L;
        int d = sl[bc] - sc - lc;         // viable_k = (k < d)

        float4 vv;
        vv.x = (d > 0) ? 1.0f : 0.0f;
        vv.y = (d > 1) ? 1.0f : 0.0f;
        vv.z = (d > 2) ? 1.0f : 0.0f;
        vv.w = (d > 3) ? 1.0f : 0.0f;
        float eb = (float)(sc + lc);
        float lnb = (float)(lc + 1);
        float fsc = (float)sc;
        float4 scv = make_float4(fsc, fsc, fsc, fsc);
        float4 ecv = make_float4(eb, eb + 1.f, eb + 2.f, eb + 3.f);
        float4 lnv = make_float4(lnb, lnb + 1.f, lnb + 2.f, lnb + 3.f);

        // ---- mapped arrays ----
        float4 fb, fs, fe, fl, pwv;
        fb.x = (float)rb[0]; fb.y = (float)rb[1]; fb.z = (float)rb[2]; fb.w = (float)rb[3];
        fs.x = (float)rs[0]; fs.y = (float)rs[1]; fs.z = (float)rs[2]; fs.w = (float)rs[3];
        fe.x = (float)(rs[0] + rl[0]); fe.y = (float)(rs[1] + rl[1]);
        fe.z = (float)(rs[2] + rl[2]); fe.w = (float)(rs[3] + rl[3]);
        fl.x = (float)(rl[0] + 1); fl.y = (float)(rl[1] + 1);
        fl.z = (float)(rl[2] + 1); fl.w = (float)(rl[3] + 1);
        pwv.x = pw[(rb[0] * S + rs[0]) * L + rl[0]];
        pwv.y = pw[(rb[1] * S + rs[1]) * L + rl[1]];
        pwv.z = pw[(rb[2] * S + rs[2]) * L + rl[2]];
        pwv.w = pw[(rb[3] * S + rs[3]) * L + rl[3]];

        size_t off6 = 5 * Nz + Nz * (size_t)L;
        __stcs((float4*)(out + i0),              vv);
        __stcs((float4*)(out + Nz + i0),         fb);
        __stcs((float4*)(out + 2 * Nz + i0),     fs);
        __stcs((float4*)(out + 3 * Nz + i0),     fe);
        __stcs((float4*)(out + 4 * Nz + i0),     fl);
        __stcs((float4*)(out + off6 + i0),       pwv);
        __stcs((float4*)(out + off6 + Nz + i0),  scv);
        __stcs((float4*)(out + off6 + 2 * Nz + i0), ecv);
        __stcs((float4*)(out + off6 + 3 * Nz + i0), lnv);

        #pragma unroll
        for (int k = 0; k < RPT; k++)
            rBS[tid * RPT + k] = (rb[k] << 16) | rs[k];
    } else {
        #pragma unroll
        for (int k = 0; k < RPT; k++) rBS[tid * RPT + k] = 0;
    }
    __syncthreads();

    // ---- unit-id matrix: block-cooperative contiguous float4 stores ----
    int nrows = N - base_row; if (nrows > ROWS_PER_BLOCK) nrows = ROWS_PER_BLOCK;
    const int nchunks = nrows * 5;
    float* ubase = out + 5 * Nz + (size_t)base_row * L;

    #pragma unroll
    for (int pass = 0; pass < RPT * 5; pass++) {
        int e = pass * TPB + tid;
        if (e < nchunks) {
            int r = (unsigned)e / 5u;
            int j = (e - r * 5) << 2;
            int bs = rBS[r];
            int s_r = bs & 0xffff;
            const int* row = seqs + (size_t)(bs >> 16) * S;
            int p0 = s_r + j;     if (p0 > maxpos) p0 = maxpos;
            int p1 = s_r + j + 1; if (p1 > maxpos) p1 = maxpos;
            int p2 = s_r + j + 2; if (p2 > maxpos) p2 = maxpos;
            int p3 = s_r + j + 3; if (p3 > maxpos) p3 = maxpos;
            float4 v;
            v.x = (float)__ldg(row + p0);
            v.y = (float)__ldg(row + p1);
            v.z = (float)__ldg(row + p2);
            v.w = (float)__ldg(row + p3);
            __stcs((float4*)(ubase + (size_t)r * L + j), v);
        }
    }
}

// ---------------- generic fallback ----------------
__global__ void __launch_bounds__(TPB)
span_generic_kernel(const int* __restrict__ seqs,
                    const int* __restrict__ lens,
                    const float* __restrict__ pw,
                    float* __restrict__ out,
                    int B, int S, int L, int N) {
    __shared__ int sp[TPB + 1];
    __shared__ int sl[TPB];
    __shared__ int wsum[8];
    __shared__ int wmax[8];
    __shared__ int rBS[TPB];

    const int tid = threadIdx.x;
    const int lane = tid & 31;
    const int warp = tid >> 5;

    int len = 0, cnt = 0;
    if (tid < B) {
        len = lens[tid];
        cnt = (len >= L) ? (len - L + 1) * L + (L * (L - 1)) / 2
                         : (len * (len + 1)) / 2;
    }
    int scn = cnt;
    #pragma unroll
    for (int o = 1; o < 32; o <<= 1) {
        int v = __shfl_up_sync(0xffffffffu, scn, o);
        if (lane >= o) scn += v;
    }
    int lmax = len;
    #pragma unroll
    for (int o = 16; o > 0; o >>= 1)
        lmax = max(lmax, __shfl_xor_sync(0xffffffffu, lmax, o));
    if (lane == 31) wsum[warp] = scn;
    if (lane == 0)  wmax[warp] = lmax;
    __syncthreads();
    int off = 0;
    #pragma unroll
    for (int k = 0; k < 8; k++) if (k < warp) off += wsum[k];
    if (tid < B) { sp[tid + 1] = scn + off; sl[tid] = len; }
    if (tid == 0) sp[0] = 0;
    int maxlen = 0;
    #pragma unroll
    for (int k = 0; k < 8; k++) maxlen = max(maxlen, wmax[k]);
    __syncthreads();

    const int i = blockIdx.x * TPB + tid;
    const int total = sp[B];
    const int maxpos = maxlen - 1;
    const size_t Nz = (size_t)N;

    int b = 0, s = 0, l = 0;
    if (i < N) {
        if (i < total) {
            int lo = 0, hi = B - 1;
            while (lo < hi) {
                int mid = (lo + hi + 1) >> 1;
                if (sp[mid] <= i) lo = mid; else hi = mid - 1;
            }
            b = lo;
            int j = i - sp[b];
            int lb = sl[b];
            int full = lb - L + 1;
            if (full > 0 && j < full * L) {
                s = j / L;
                l = j - s * L;
            } else {
                int s0 = full > 0 ? full : 0;
                int jp = j - (full > 0 ? full * L : 0);
                int ss = s0, c = 0;
                while (true) {
                    int m = lb - ss; if (m > L) m = L;
                    if (jp < c + m) { l = jp - c; break; }
                    c += m; ss++;
                }
                s = ss;
            }
        }

        int SL = S * L;
        int bc = i / SL;
        int rem = i - bc * SL;
        int sc = rem / L;
        int lc = rem - sc * L;
        float viable_f = ((sc + lc) < sl[bc]) ? 1.0f : 0.0f;

        out[i]          = viable_f;
        out[Nz + i]     = (float)b;
        out[2 * Nz + i] = (float)s;
        out[3 * Nz + i] = (float)(s + l);
        out[4 * Nz + i] = (float)(l + 1);

        size_t off6 = 5 * Nz + Nz * (size_t)L;
        out[off6 + i]          = pw[((size_t)b * S + s) * L + l];
        out[off6 + Nz + i]     = (float)sc;
        out[off6 + 2 * Nz + i] = (float)(sc + lc);
        out[off6 + 3 * Nz + i] = (float)(lc + 1);
    }

    rBS[tid] = (b << 16) | s;
    __syncthreads();

    const int base_row = blockIdx.x * TPB;
    int nrows = N - base_row; if (nrows > TPB) nrows = TPB;

    for (int e = tid; e < nrows * L; e += TPB) {
        int r = e / L;
        int j = e - r * L;
        int bs = rBS[r];
        int p = (bs & 0xffff) + j; if (p > maxpos) p = maxpos;
        out[5 * Nz + (size_t)(base_row + r) * L + j] =
            (float)seqs[(size_t)(bs >> 16) * S + p];
    }
}

extern "C" void kernel_launch(void* const* d_in, const int* in_sizes, int n_in,
                              void* d_out, int out_size) {
    const int* seqs = (const int*)d_in[0];   // (B, S) int32
    const int* lens = (const int*)d_in[1];   // (B,)   int32
    const float* pw = (const float*)d_in[2]; // (B, S, L) float32

    int B = in_sizes[1];
    int S = in_sizes[0] / B;
    int N = in_sizes[2];          // B*S*L
    int L = N / (B * S);
    float* out = (float*)d_out;

    if (B == SP_B && S == SP_S && L == SP_L) {
        int blocks = (N + ROWS_PER_BLOCK - 1) / ROWS_PER_BLOCK;
        span_main_kernel<<<blocks, TPB>>>(seqs, lens, pw, out, N);
    } else {
        int blocks = (N + TPB - 1) / TPB;
        span_generic_kernel<<<blocks, TPB>>>(seqs, lens, pw, out, B, S, L, N);
    }
}